// round 16
// baseline (speedup 1.0000x reference)
#include <cuda_runtime.h>
#include <math.h>
#include <float.h>
#include <stdint.h>

// Problem constants
#define Bn 32
#define Mn 384
#define Nn 128
#define Cn 92

static __device__ __constant__ float kCOST_IOU = 2.0f;
static __device__ __constant__ float kCOST_L1  = 5.0f;
static __device__ __constant__ float kCOST_CAT = 1.0f;
static __device__ __constant__ float kEPS      = 1e-7f;

// Scratch (device globals: allocation-free)
__device__ float  g_cost[(size_t)Bn * Nn * Mn];   // [b][n][m]
__device__ float2 g_stats[Bn * Mn];               // (max, sumexp) per (b,m)
__device__ float4 g_pxy[Bn * Mn];                 // pred xyxy
__device__ float4 g_txy[Bn * Nn];                 // targ xyxy
__device__ int    g_assign[Bn * Nn];
__device__ float  g_loss[Bn];
__device__ int    g_done;

// ---------------------------------------------------------------------------
// Kernel 1: per-(b,m) softmax stats + pred xyxy; per-(b,n) targ xyxy
// ---------------------------------------------------------------------------
__global__ void prep_kernel(const float* __restrict__ pred_cat,
                            const float* __restrict__ pred_bbox,
                            const float* __restrict__ targ_bbox) {
    int t = blockIdx.x * blockDim.x + threadIdx.x;
    if (t == 0) g_done = 0;                      // reset ticket each replay
    if (t < Bn * Mn) {
        const float4* r4 = (const float4*)(pred_cat + (size_t)t * Cn);
        float mx = -FLT_MAX;
        #pragma unroll
        for (int q = 0; q < Cn / 4; q++) {
            float4 v = r4[q];
            mx = fmaxf(mx, v.x); mx = fmaxf(mx, v.y);
            mx = fmaxf(mx, v.z); mx = fmaxf(mx, v.w);
        }
        float s = 0.0f;
        #pragma unroll
        for (int q = 0; q < Cn / 4; q++) {
            float4 v = r4[q];
            s += expf(v.x - mx); s += expf(v.y - mx);
            s += expf(v.z - mx); s += expf(v.w - mx);
        }
        g_stats[t] = make_float2(mx, s);
        const float* pb = pred_bbox + (size_t)t * 4;
        float cx = pb[0], cy = pb[1], w = pb[2], h = pb[3];
        g_pxy[t] = make_float4(cx - 0.5f * w, cy - 0.5f * h,
                               cx + 0.5f * w, cy + 0.5f * h);
    } else if (t < Bn * Mn + Bn * Nn) {
        int u = t - Bn * Mn;
        float cx = targ_bbox[u * 4 + 0], cy = targ_bbox[u * 4 + 1];
        float w  = targ_bbox[u * 4 + 2], h  = targ_bbox[u * 4 + 3];
        g_txy[u] = make_float4(cx - 0.5f * w, cy - 0.5f * h,
                               cx + 0.5f * w, cy + 0.5f * h);
    }
}

// GIoU-loss + L1 helper (matches reference formula order)
__device__ __forceinline__ float bbox_pair_cost(float4 p, float4 t) {
    float ix1 = fmaxf(p.x, t.x), iy1 = fmaxf(p.y, t.y);
    float ix2 = fminf(p.z, t.z), iy2 = fminf(p.w, t.w);
    float inter = fmaxf(ix2 - ix1, 0.0f) * fmaxf(iy2 - iy1, 0.0f);
    float ap = (p.z - p.x) * (p.w - p.y);
    float at = (t.z - t.x) * (t.w - t.y);
    float un = ap + at - inter;
    float iou = inter / (un + kEPS);
    float cx1 = fminf(p.x, t.x), cy1 = fminf(p.y, t.y);
    float cx2 = fmaxf(p.z, t.z), cy2 = fmaxf(p.w, t.w);
    float ac = (cx2 - cx1) * (cy2 - cy1);
    float giou = iou - (ac - un) / (ac + kEPS);
    float gl = 1.0f - giou;
    float l1 = (fabsf(p.x - t.x) + fabsf(p.y - t.y) +
                fabsf(p.z - t.z) + fabsf(p.w - t.w)) * 0.25f;
    return kCOST_IOU * gl + kCOST_L1 * l1;
}

// ---------------------------------------------------------------------------
// Kernel 2: cost matrix, one block per (b,n), thread per m (coalesced writes)
// ---------------------------------------------------------------------------
__global__ __launch_bounds__(Mn) void cost_kernel(const float* __restrict__ pred_cat,
                                                  const int* __restrict__ targ_cat) {
    int b = blockIdx.y, n = blockIdx.x, m = threadIdx.x;
    int tc = targ_cat[b * Nn + n];
    float4 t4 = g_txy[b * Nn + n];
    float maskf = (tc != 0) ? 1.0f : 0.0f;

    float2 st = g_stats[b * Mn + m];
    float logit = pred_cat[((size_t)(b * Mn + m)) * Cn + tc];
    float prob = expf(logit - st.x) / st.y;
    float cat = kCOST_CAT * (1.0f - prob);

    float bb = bbox_pair_cost(g_pxy[b * Mn + m], t4);
    g_cost[((size_t)(b * Nn + n)) * Mn + m] = cat + bb * maskf;
}

// ---------------------------------------------------------------------------
// Kernel 3: Hungarian (JV) — block-per-batch, 384 threads, 1 col/thread.
// ONE barrier per step. Packed ulonglong2 staging (1 ST.128 / 1 LDS.128).
// Next-row pre-add computed BEFORE the end-of-row barrier (u[i+1]==0 until
// row i+1 starts, so it's independent of the augment chase -> overlapped).
// f64 duals, numpy op order, exact lowest-index tie-break via u64 keys.
// ---------------------------------------------------------------------------
#define CS_BYTES   (Nn * Mn * 4)             // 196608
#define OFF_U      (CS_BYTES)                // double[Nn+1]
#define OFF_P      (OFF_U + (Nn + 1) * 8)    // int[Mn+1]
#define OFF_WAY    (OFF_P + (Mn + 1) * 4)    // int[Mn+1]
#define SMEM_TOTAL (OFF_WAY + (Mn + 1) * 4)  // ~200 KB dynamic

__device__ __forceinline__ unsigned long long dkey(double d) {
    unsigned long long b = (unsigned long long)__double_as_longlong(d);
    return (b & 0x8000000000000000ull) ? ~b : (b | 0x8000000000000000ull);
}
__device__ __forceinline__ double dunkey(unsigned long long k) {
    unsigned long long b = (k & 0x8000000000000000ull)
                         ? (k & 0x7FFFFFFFFFFFFFFFull) : ~k;
    return __longlong_as_double((long long)b);
}

__global__ __launch_bounds__(Mn, 1) void hungarian_kernel(
        const float* __restrict__ pred_cat,
        const int* __restrict__ targ_cat,
        float* __restrict__ out, int mode) {
    const unsigned FULL = 0xffffffffu;
    int b = blockIdx.x;
    extern __shared__ unsigned char smem[];
    float*  cs   = (float*)smem;
    double* u_sh = (double*)(smem + OFF_U);
    int*    p_sh = (int*)(smem + OFF_P);
    int*    way  = (int*)(smem + OFF_WAY);

    __shared__ ulonglong2 wrec[2][12];   // {key, mycol<<32 | my_p}
    __shared__ int   a_sh[Nn];
    __shared__ float r1[4], r2[4], r3[4];
    __shared__ int   ticket;

    int tid = threadIdx.x;
    int wid = tid >> 5, lane = tid & 31;
    const int mycol = tid + 1;
    const double DINF = (double)INFINITY;

    // ---- stage cost tile into smem (float4) ----
    {
        const float4* gc = (const float4*)(g_cost + (size_t)b * Nn * Mn);
        float4* c4 = (float4*)cs;
        #pragma unroll 4
        for (int idx = tid; idx < Nn * Mn / 4; idx += Mn) c4[idx] = gc[idx];
    }
    p_sh[mycol] = 0;
    if (tid <= Nn) u_sh[tid] = 0.0;
    __syncthreads();

    double v_reg = 0.0, minv;
    bool used;
    int my_p;
    int parity = 0;
    // first row's hoisted pre-add: (cost - u[1]), u[1]==0
    double pre = (double)cs[0 * Mn + tid] - u_sh[1];

    for (int i = 1; i <= Nn; i++) {
        minv = DINF;
        used = false;
        my_p = p_sh[mycol];              // after augment BAR; stable in path
        int j0 = 0;

        while (true) {
            unsigned long long key;
            if (!used) {
                double cur = pre - v_reg;
                if (cur < minv) { minv = cur; way[mycol] = j0; }
                key = dkey(minv);
            } else {
                key = 0xFFFFFFFFFFFFFFFFull;
            }
            unsigned fk = (unsigned)(key >> 32);   // monotone top-32 of key

            // warp stage: winner writes its OWN packed record (one ST.128)
            {
                unsigned rhi = __reduce_min_sync(FULL, fk);
                unsigned bal = __ballot_sync(FULL, fk == rhi);
                bool win;
                if (__popc(bal) == 1) {            // warp-uniform branch
                    win = (fk == rhi);
                } else {
                    unsigned cand = (fk == rhi) ? (unsigned)key : 0xFFFFFFFFu;
                    unsigned rlo  = __reduce_min_sync(FULL, cand);
                    unsigned bal2 = __ballot_sync(FULL,
                                        (fk == rhi) & (cand == rlo));
                    win = (lane == __ffs(bal2) - 1);
                }
                if (win) {
                    ulonglong2 r;
                    r.x = key;
                    r.y = ((unsigned long long)mycol << 32) | (unsigned)my_p;
                    wrec[parity][wid] = r;
                }
            }
            __syncthreads();                      // the ONLY barrier per step

            // block stage: EVERY warp reduces the 12 packed records
            double delta; int k, k_p;
            {
                ulonglong2 rec;
                if (lane < 12) {
                    rec = wrec[parity][lane];
                } else {
                    rec.x = 0xFFFFFFFFFFFFFFFFull;
                    rec.y = 0x7FFFFFFF00000000ull;
                }
                unsigned hi2  = (unsigned)(rec.x >> 32);
                unsigned rhi2 = __reduce_min_sync(FULL, hi2);
                unsigned b2   = __ballot_sync(FULL, hi2 == rhi2);
                int wlane;
                if (__popc(b2) == 1) {
                    wlane = __ffs(b2) - 1;
                } else {
                    unsigned cand2 = (hi2 == rhi2) ? (unsigned)rec.x : 0xFFFFFFFFu;
                    unsigned rlo2  = __reduce_min_sync(FULL, cand2);
                    unsigned b3    = __ballot_sync(FULL,
                                        (hi2 == rhi2) & (cand2 == rlo2));
                    wlane = __ffs(b3) - 1;        // lowest lane = lowest column
                }
                unsigned long long kk = __shfl_sync(FULL, rec.x, wlane);
                unsigned long long py = __shfl_sync(FULL, rec.y, wlane);
                k   = (int)(py >> 32);
                k_p = (int)(py & 0xFFFFFFFFull);
                delta = dunkey(kk);               // exact f64 minv[k]
            }

            // prefetch NEXT step's row + u and hoist the first subtraction.
            // Safe: rows updated below (rows of used cols + row i) are all
            // distinct from k_p (row matched to the still-free column k).
            int rowbase = (k_p > 0) ? (k_p - 1) * Mn : 0;
            float  c_next = cs[rowbase + tid];
            double u_next = u_sh[(k_p > 0) ? k_p : 0];
            double pre_next = (double)c_next - u_next;   // overlaps updates

            // dual updates (numpy f64 op order; rows disjoint across threads)
            if (used) {
                v_reg -= delta;
                u_sh[my_p] += delta;
            } else {
                minv -= delta;
            }
            if (tid == 0) u_sh[i] += delta;       // virtual column 0 (p[0]=i)

            // numpy marks used[j0] at next-iteration top == mark k here
            if (mycol == k) used = true;

            parity ^= 1;
            j0 = k; pre = pre_next;
            if (k_p == 0) break;
        }

        // Overlap: next row's pre-add is independent of the augment chase
        // (u[i+1]==0 until row i+1 starts; cs is read-only) -> compute NOW.
        if (i < Nn) pre = (double)cs[i * Mn + tid] - u_sh[i + 1];

        // augment along alternating path (thread 0; way[] visible via BAR)
        if (tid == 0) {
            int jj = j0;
            while (jj) {
                int j1 = way[jj];
                p_sh[jj] = (j1 == 0) ? i : p_sh[j1];
                jj = j1;
            }
        }
        __syncthreads();
    }

    // ---- write assignment (direct to out for mode 0) + inverse map ----
    {
        int pi = p_sh[mycol];
        if (pi > 0) {
            int a = mycol - 1;
            g_assign[b * Nn + (pi - 1)] = a;
            a_sh[pi - 1] = a;
            if (mode == 0)      out[1 + b * Nn + (pi - 1)] = (float)a;
            else if (mode == 1) out[b * Nn + (pi - 1)]     = (float)a;
        }
    }
    __syncthreads();

    // ---- fused per-batch loss ----
    float s_ce = 0.0f, s_bl = 0.0f, s_mk = 0.0f;
    if (tid < Nn) {
        int n  = tid;
        int a  = a_sh[n];
        int tc = targ_cat[b * Nn + n];
        float2 st = g_stats[b * Mn + a];
        float logit = pred_cat[((size_t)(b * Mn + a)) * Cn + tc];
        s_ce = -(logit - st.x - logf(st.y));
        float bl = bbox_pair_cost(g_pxy[b * Mn + a], g_txy[b * Nn + n]);
        s_mk = (tc != 0) ? 1.0f : 0.0f;
        s_bl = bl * s_mk;
    }
    #pragma unroll
    for (int off = 16; off; off >>= 1) {
        s_ce += __shfl_down_sync(FULL, s_ce, off);
        s_bl += __shfl_down_sync(FULL, s_bl, off);
        s_mk += __shfl_down_sync(FULL, s_mk, off);
    }
    if (wid < 4 && lane == 0) { r1[wid] = s_ce; r2[wid] = s_bl; r3[wid] = s_mk; }
    __syncthreads();
    if (tid == 0) {
        float ce_sum = r1[0] + r1[1] + r1[2] + r1[3];
        float bl_sum = r2[0] + r2[1] + r2[2] + r2[3];
        float mk_sum = r3[0] + r3[1] + r3[2] + r3[3];
        g_loss[b] = (ce_sum / (float)Nn) + bl_sum / (mk_sum + kEPS);
        __threadfence();
        ticket = atomicAdd(&g_done, 1);
    }
    __syncthreads();

    // last-arriving block reduces the 32 losses (fixed order: deterministic)
    if (tid == 0 && ticket == Bn - 1 && (mode == 0 || mode == 2)) {
        __threadfence();
        float s = 0.0f;
        for (int bb = 0; bb < Bn; bb++) s += g_loss[bb];
        out[0] = s / (float)Bn;
    }
}

// ---------------------------------------------------------------------------
// Finalize (only for fallback modes; mode 0 handled in-solver)
// ---------------------------------------------------------------------------
__global__ void finalize_kernel(float* __restrict__ out, int mode) {
    int t = blockIdx.x * blockDim.x + threadIdx.x;
    if (mode == 1) {
        if (t < Bn * Nn) out[t] = (float)g_assign[t];
    } else {
        if (t == 0) {
            float s = 0.0f;
            for (int b = 0; b < Bn; b++) s += g_loss[b];
            out[0] = s / (float)Bn;
        }
    }
}

// ---------------------------------------------------------------------------
extern "C" void kernel_launch(void* const* d_in, const int* in_sizes, int n_in,
                              void* d_out, int out_size) {
    const float* pred_cat  = (const float*)d_in[0];
    const float* pred_bbox = (const float*)d_in[1];
    const int*   targ_cat  = (const int*)d_in[2];
    const float* targ_bbox = (const float*)d_in[3];
    float* out = (float*)d_out;

    int mode;
    if (out_size == Bn * Nn + 1)      mode = 0;
    else if (out_size == Bn * Nn)     mode = 1;
    else                              mode = 2;

    int tot = Bn * Mn + Bn * Nn;
    prep_kernel<<<(tot + 127) / 128, 128>>>(pred_cat, pred_bbox, targ_bbox);

    dim3 gc(Nn, Bn);
    cost_kernel<<<gc, Mn>>>(pred_cat, targ_cat);

    cudaFuncSetAttribute(hungarian_kernel,
                         cudaFuncAttributeMaxDynamicSharedMemorySize, SMEM_TOTAL);
    hungarian_kernel<<<Bn, Mn, SMEM_TOTAL>>>(pred_cat, targ_cat, out, mode);

    if (mode != 0)
        finalize_kernel<<<(Bn * Nn + 127) / 128, 128>>>(out, mode);
}